// round 14
// baseline (speedup 1.0000x reference)
#include <cuda_runtime.h>
#include <cuda_bf16.h>
#include <cstdint>

// ---------------------------------------------------------------------------
// Problem constants
// ---------------------------------------------------------------------------
#define T_LEN   262144
#define B_N     16
#define W_LEN   8640
#define PAD     4320
#define F_META  8

// GEMM decomposition (r9-proven inner shape)
#define JT      1024              // taps per x chunk (64 k16-steps)
#define NCHK    9                 // chunks (576 steps >= 571+1)
#define XSROW   1040              // x smem pitch elems; conflict-free LDS.64
#define WBUF    9792              // guarded weight buffer elems
#define WOFF    512
#define XPITCH  271872            // gxp row pitch elems

// smem byte offsets (r9 layout)
#define WH_OFF   0
#define WL_OFF   19584
#define XSH_OFF  39168
#define XSL_OFF  72448
#define SMEM_SZ  105728

#define NSLOT    2048             // 128-row blocks for mean partials

// ---------------------------------------------------------------------------
// Device scratch (no cudaMalloc allowed)
// ---------------------------------------------------------------------------
__device__ float g_w[W_LEN];
__device__ __align__(16) unsigned short g_wh[WBUF];
__device__ __align__(16) unsigned short g_wl[WBUF];
__device__ __align__(16) unsigned short gxph[B_N * XPITCH];   // frag-packed
__device__ __align__(16) unsigned short gxpl[B_N * XPITCH];
__device__ float g_part2[B_N * NSLOT];    // per-(n, 128-row block) mean partials
__device__ float g_scale[B_N];

// ---------------------------------------------------------------------------
// Helpers
// ---------------------------------------------------------------------------
__device__ __forceinline__ uint32_t pk(const unsigned short* p) {
    return (uint32_t)p[0] | ((uint32_t)p[1] << 16);
}
__device__ __forceinline__ void mma16816(float* d, uint32_t a0, uint32_t a1,
                                         uint32_t a2, uint32_t a3,
                                         uint32_t b0, uint32_t b1) {
    asm volatile(
        "mma.sync.aligned.m16n8k16.row.col.f32.bf16.bf16.f32 "
        "{%0,%1,%2,%3}, {%4,%5,%6,%7}, {%8,%9}, {%0,%1,%2,%3};"
        : "+f"(d[0]), "+f"(d[1]), "+f"(d[2]), "+f"(d[3])
        : "r"(a0), "r"(a1), "r"(a2), "r"(a3), "r"(b0), "r"(b1));
}

// ---------------------------------------------------------------------------
// Prep 1: softmax over temporal_weights, flipped -> g_w
// ---------------------------------------------------------------------------
__global__ void softmax_flip_kernel(const float* __restrict__ tw) {
    __shared__ float red[256];
    __shared__ float s_max, s_invsum;
    const int tid = threadIdx.x;

    float m = -1e30f;
    for (int i = tid; i < W_LEN; i += 256) m = fmaxf(m, tw[i]);
    red[tid] = m; __syncthreads();
    for (int s = 128; s > 0; s >>= 1) {
        if (tid < s) red[tid] = fmaxf(red[tid], red[tid + s]);
        __syncthreads();
    }
    if (tid == 0) s_max = red[0];
    __syncthreads();
    const float mx = s_max;
    __syncthreads();

    float sum = 0.f;
    for (int i = tid; i < W_LEN; i += 256) sum += expf(tw[i] - mx);
    red[tid] = sum; __syncthreads();
    for (int s = 128; s > 0; s >>= 1) {
        if (tid < s) red[tid] += red[tid + s];
        __syncthreads();
    }
    if (tid == 0) s_invsum = 1.f / red[0];
    __syncthreads();
    const float inv = s_invsum;

    for (int i = tid; i < W_LEN; i += 256)
        g_w[W_LEN - 1 - i] = expf(tw[i] - mx) * inv;
}

// ---------------------------------------------------------------------------
// Prep 2: guarded split-bf16 weight buffer
// ---------------------------------------------------------------------------
__global__ void wsplit_kernel() {
    for (int i = threadIdx.x; i < WBUF; i += 256) {
        int wi = i - WOFF;
        float v = (wi >= 0 && wi < W_LEN) ? g_w[wi] : 0.f;
        __nv_bfloat16 h = __float2bfloat16(v);
        float lo = v - __bfloat162float(h);
        __nv_bfloat16 l = __float2bfloat16(lo);
        g_wh[i] = __bfloat16_as_ushort(h);
        g_wl[i] = __bfloat16_as_ushort(l);
    }
}

// ---------------------------------------------------------------------------
// Prep 3: edge-padded split-bf16 input planes, FRAGMENT-PACKED.
// Also zeroes the mean-partial slots (re-zeroed every launch for graph replay).
// ---------------------------------------------------------------------------
__global__ void xsplit_kernel(const float* __restrict__ att) {
    long long idx = (long long)blockIdx.x * blockDim.x + threadIdx.x;
    if (idx < B_N * NSLOT) g_part2[idx] = 0.f;
    if (idx >= (long long)B_N * XPITCH) return;
    int n = (int)(idx / XPITCH);
    int u = (int)(idx - (long long)n * XPITCH);
    int t = u - PAD;
    t = min(max(t, 0), T_LEN - 1);
    float v = att[n * T_LEN + t];
    __nv_bfloat16 h = __float2bfloat16(v);
    float lo = v - __bfloat162float(h);
    __nv_bfloat16 l = __float2bfloat16(lo);
    int g = u >> 4, p = u & 15;
    int np = (p < 8) ? (((p >> 1) << 2) | (p & 1))
                     : ((((p - 8) >> 1) << 2) | 2 | (p & 1));
    size_t dst = (size_t)n * XPITCH + (g << 4) + np;
    gxph[dst] = __bfloat16_as_ushort(h);
    gxpl[dst] = __bfloat16_as_ushort(l);
}

// ---------------------------------------------------------------------------
// Tiered GEMM body.  IB = m-blocks per warp (4/2/1 -> 512/256/128-row tiles).
// 8 warps, r9 machinery: single-buffer LDG/STS staging, ring-4 Toeplitz A
// chaining, LDS.64 frag-packed B, 3-pass split-bf16, band skip.
// ---------------------------------------------------------------------------
template <int IB>
__device__ __forceinline__ void gemm_body(float* __restrict__ out, int t0,
                                          unsigned char* smem) {
    constexpr int MT = 128 * IB;          // tile rows
    constexpr int PITCH = MT + 8;
    unsigned short* wh = (unsigned short*)(smem + WH_OFF);
    unsigned short* wl = (unsigned short*)(smem + WL_OFF);
    unsigned short* xsh = (unsigned short*)(smem + XSH_OFF);
    unsigned short* xsl = (unsigned short*)(smem + XSL_OFF);

    const int tid  = threadIdx.x;
    const int warp = tid >> 5;
    const int lane = tid & 31;
    const int Wbase = warp * 16 * IB;
    const int r0 = lane >> 2;
    const int c0 = (lane & 3) * 2;
    const int smin = IB * warp;
    const int smax = IB * (warp + 1) + 539;

    // stage weights (38.3 KB) once
    for (int i = tid; i < WBUF / 8; i += 256) {
        ((uint4*)wh)[i] = ((const uint4*)g_wh)[i];
        ((uint4*)wl)[i] = ((const uint4*)g_wl)[i];
    }

    const unsigned short* bh0 = xsh + (lane >> 2) * XSROW + 2 * c0;
    const unsigned short* bh1 = xsh + ((lane >> 2) + 8) * XSROW + 2 * c0;
    const unsigned short* bl0 = xsl + (lane >> 2) * XSROW + 2 * c0;
    const unsigned short* bl1 = xsl + ((lane >> 2) + 8) * XSROW + 2 * c0;

    float acc[IB][2][4];
#pragma unroll
    for (int i = 0; i < IB; i++)
#pragma unroll
        for (int nb = 0; nb < 2; nb++)
#pragma unroll
            for (int q = 0; q < 4; q++) acc[i][nb][q] = 0.f;

    uint32_t Ah[4][3], Al[4][3];
#pragma unroll
    for (int i = 0; i < 4; i++)
#pragma unroll
        for (int q = 0; q < 3; q++) { Ah[i][q] = 0u; Al[i][q] = 0u; }

    for (int chunk = 0; chunk < NCHK; ++chunk) {
        __syncthreads();
        // stage x chunk: 16 rows x 1024 elems x 2 planes (64 KB)
        {
            const int xbase = t0 + chunk * JT;
            for (int it = tid; it < 4096; it += 256) {
                int plane = it >> 11;
                int r = (it >> 7) & 15;
                int q = it & 127;
                const unsigned short* src =
                    (plane ? gxpl : gxph) + (size_t)r * XPITCH + xbase + q * 8;
                unsigned short* dst = (plane ? xsl : xsh) + r * XSROW + q * 8;
                *(uint4*)dst = *(const uint4*)src;
            }
        }
        __syncthreads();

        const int s0 = chunk * 64;
        int sl_lo = smin - s0; if (sl_lo < 0) sl_lo = 0;
        int sl_hi = smax - s0; if (sl_hi > 63) sl_hi = 63;
        if (sl_lo > sl_hi) continue;

        uint32_t pAh, pAl;
        {
            const int base0 = WOFF + 16 * (s0 + sl_lo) - Wbase + c0 - r0;
            pAh = pk(wh + base0 - 8);
            pAl = pk(wl + base0 - 8);
        }

#pragma unroll 4
        for (int sl = sl_lo; sl <= sl_hi; ++sl) {
            const int s = s0 + sl;
            const int slot = sl & 3;
            const int base = WOFF + 16 * s - Wbase + c0 - r0;
            Ah[slot][1] = pAh;               Al[slot][1] = pAl;
            Ah[slot][0] = pk(wh + base);     Al[slot][0] = pk(wl + base);
            Ah[slot][2] = pk(wh + base + 8); Al[slot][2] = pk(wl + base + 8);
            pAh = Ah[slot][2];               pAl = Al[slot][2];

            const int jj = 16 * sl;
            uint2 vh0 = *(const uint2*)(bh0 + jj);
            uint2 vh1 = *(const uint2*)(bh1 + jj);
            uint2 vl0 = *(const uint2*)(bl0 + jj);
            uint2 vl1 = *(const uint2*)(bl1 + jj);
            uint32_t bh[2][2] = {{vh0.x, vh0.y}, {vh1.x, vh1.y}};
            uint32_t bl[2][2] = {{vl0.x, vl0.y}, {vl1.x, vl1.y}};

#pragma unroll
            for (int ib = 0; ib < IB; ++ib) {
                const int sig = (sl - ib) & 3;
                mma16816(acc[ib][0], Ah[sig][0], Ah[sig][1], Ah[sig][2], Ah[sig][0], bh[0][0], bh[0][1]);
                mma16816(acc[ib][1], Ah[sig][0], Ah[sig][1], Ah[sig][2], Ah[sig][0], bh[1][0], bh[1][1]);
            }
#pragma unroll
            for (int ib = 0; ib < IB; ++ib) {
                const int sig = (sl - ib) & 3;
                mma16816(acc[ib][0], Ah[sig][0], Ah[sig][1], Ah[sig][2], Ah[sig][0], bl[0][0], bl[0][1]);
                mma16816(acc[ib][1], Ah[sig][0], Ah[sig][1], Ah[sig][2], Ah[sig][0], bl[1][0], bl[1][1]);
            }
#pragma unroll
            for (int ib = 0; ib < IB; ++ib) {
                const int sig = (sl - ib) & 3;
                mma16816(acc[ib][0], Al[sig][0], Al[sig][1], Al[sig][2], Al[sig][0], bh[0][0], bh[0][1]);
                mma16816(acc[ib][1], Al[sig][0], Al[sig][1], Al[sig][2], Al[sig][0], bh[1][0], bh[1][1]);
            }
        }
    }

    // ---- epilogue: transpose via smt (over dead weights), mean partials ----
    __syncthreads();
    float* smt = (float*)smem;               // 16 x PITCH floats <= 33.3 KB
#pragma unroll
    for (int ib = 0; ib < IB; ++ib) {
        const int mloc = Wbase + ib * 16 + r0;
#pragma unroll
        for (int nb = 0; nb < 2; ++nb) {
            const int n = c0 + nb * 8;
            smt[n * PITCH + mloc]           = acc[ib][nb][0];
            smt[(n + 1) * PITCH + mloc]     = acc[ib][nb][1];
            smt[n * PITCH + mloc + 8]       = acc[ib][nb][2];
            smt[(n + 1) * PITCH + mloc + 8] = acc[ib][nb][3];
        }
    }
    __syncthreads();

    // deterministic per-CTA per-n partial sums (warp w -> n=w and n=w+8)
    {
        float sa = 0.f, sb = 0.f;
        for (int m = lane; m < MT; m += 32) {
            sa += smt[warp * PITCH + m];
            sb += smt[(warp + 8) * PITCH + m];
        }
#pragma unroll
        for (int o = 16; o > 0; o >>= 1) {
            sa += __shfl_xor_sync(0xFFFFFFFFu, sa, o);
            sb += __shfl_xor_sync(0xFFFFFFFFu, sb, o);
        }
        if (lane == 0) {
            int slot = t0 >> 7;
            g_part2[warp * NSLOT + slot] = sa;
            g_part2[(warp + 8) * NSLOT + slot] = sb;
        }
    }

    for (int e = tid; e < B_N * MT; e += 256) {
        int n = e / MT;
        int mloc = e - n * MT;
        out[n * T_LEN + t0 + mloc] = smt[n * PITCH + mloc];
    }
}

__global__ void __launch_bounds__(256, 2) gemm_kernel(float* __restrict__ out,
                                                      int n1, int n2) {
    extern __shared__ unsigned char smem[];
    const int bid = blockIdx.x;
    if (bid < n1) {
        gemm_body<4>(out, bid * 512, smem);
    } else if (bid < n1 + n2) {
        gemm_body<2>(out, n1 * 512 + (bid - n1) * 256, smem);
    } else {
        gemm_body<1>(out, n1 * 512 + n2 * 256 + (bid - n1 - n2) * 128, smem);
    }
}

// ---------------------------------------------------------------------------
// MLP: parallel mean gather (16 warps, one per batch) + tiny MLP
// ---------------------------------------------------------------------------
__global__ void mlp_kernel(const float* __restrict__ meta,
                           const float* __restrict__ W1, const float* __restrict__ b1,
                           const float* __restrict__ W2, const float* __restrict__ b2,
                           const float* __restrict__ W3, const float* __restrict__ b3,
                           const float* __restrict__ cs) {
    __shared__ float s_mean[B_N];
    const int tid = threadIdx.x;
    const int n = tid >> 5, l = tid & 31;

    float s = 0.f;
    for (int j = l; j < NSLOT; j += 32) s += g_part2[n * NSLOT + j];
#pragma unroll
    for (int o = 16; o > 0; o >>= 1) s += __shfl_xor_sync(0xFFFFFFFFu, s, o);
    if (l == 0) s_mean[n] = s;
    __syncthreads();

    const int b = tid;
    if (b >= B_N) return;

    float ci[1 + F_META];
    ci[0] = s_mean[b] / (float)T_LEN;
    for (int i = 0; i < F_META; ++i) ci[1 + i] = meta[b * F_META + i];

    float h1[32];
    for (int j = 0; j < 32; ++j) {
        float a = b1[j];
        for (int i = 0; i < 1 + F_META; ++i) a = fmaf(W1[j * (1 + F_META) + i], ci[i], a);
        h1[j] = fmaxf(a, 0.f);
    }
    float h2[16];
    for (int j = 0; j < 16; ++j) {
        float a = b2[j];
        for (int i = 0; i < 32; ++i) a = fmaf(W2[j * 32 + i], h1[i], a);
        h2[j] = fmaxf(a, 0.f);
    }
    float f = b3[0];
    for (int i = 0; i < 16; ++i) f = fmaf(W3[i], h2[i], f);
    g_scale[b] = 1.f + cs[0] * tanhf(f);
}

__global__ void scale_kernel(float* __restrict__ out) {
    int idx = blockIdx.x * blockDim.x + threadIdx.x;
    const int per_b = T_LEN / 4;
    int b = idx / per_b;
    float s = g_scale[b];
    float4* o4 = (float4*)out;
    float4 v = o4[idx];
    v.x *= s; v.y *= s; v.z *= s; v.w *= s;
    o4[idx] = v;
}

// ---------------------------------------------------------------------------
// Launch
// ---------------------------------------------------------------------------
extern "C" void kernel_launch(void* const* d_in, const int* in_sizes, int n_in,
                              void* d_out, int out_size) {
    const float* att  = (const float*)d_in[0];
    const float* meta = (const float*)d_in[1];
    const float* tw   = (const float*)d_in[2];
    const float* W1   = (const float*)d_in[3];
    const float* b1   = (const float*)d_in[4];
    const float* W2   = (const float*)d_in[5];
    const float* b2   = (const float*)d_in[6];
    const float* W3   = (const float*)d_in[7];
    const float* b3   = (const float*)d_in[8];
    const float* cs   = (const float*)d_in[9];
    float* out = (float*)d_out;

    int nsm = 148;
    cudaDeviceGetAttribute(&nsm, cudaDevAttrMultiProcessorCount, 0);
    if (nsm <= 0 || nsm > 1024) nsm = 148;
    const int slots = 2 * nsm;

    // tiered grid: n1 full 512-row tiles (1 wave), n2 half tiles, n3 quarter
    int total = 512;                       // 512-row tile equivalents
    int n1 = slots < total ? slots : total;
    int remT = total - n1;                 // in full-tile units
    int n2 = 2 * remT; if (n2 > slots) n2 = slots;  // 256-row CTAs
    int remT2 = remT - n2 / 2;
    int n3 = 4 * remT2;                    // 128-row CTAs
    if (n3 < 0) n3 = 0;

    cudaFuncSetAttribute(gemm_kernel, cudaFuncAttributeMaxDynamicSharedMemorySize, SMEM_SZ);

    softmax_flip_kernel<<<1, 256>>>(tw);
    wsplit_kernel<<<1, 256>>>();
    {
        long long tot = (long long)B_N * XPITCH;
        int blocks = (int)((tot + 255) / 256);
        xsplit_kernel<<<blocks, 256>>>(att);
    }
    gemm_kernel<<<n1 + n2 + n3, 256, SMEM_SZ>>>(out, n1, n2);
    mlp_kernel<<<1, 512>>>(meta, W1, b1, W2, b2, W3, b3, cs);
    scale_kernel<<<(B_N * T_LEN / 4 + 255) / 256, 256>>>(out);
}

// round 17
// speedup vs baseline: 1.6307x; 1.6307x over previous
#include <cuda_runtime.h>
#include <cuda_bf16.h>
#include <cstdint>

// ---------------------------------------------------------------------------
// Problem constants
// ---------------------------------------------------------------------------
#define T_LEN   262144
#define B_N     16
#define W_LEN   8640
#define PAD     4320
#define F_META  8

// GEMM decomposition (r9-proven inner shape)
#define JT      1024              // taps per x chunk (64 k16-steps)
#define NCHK    9                 // chunks (576 steps)
#define XSROW   1040              // x smem pitch elems; conflict-free LDS.64
#define WBUF    9792              // guarded weight buffer elems
#define WOFF    512
#define XPITCH  271872            // gxp row pitch elems

// Two-tier grid: 293 x 512-row CTAs + 292 x 384-row CTAs = 262144 rows exactly
#define N1      293
#define N2      292

// smem byte offsets (r9 layout)
#define WH_OFF   0
#define WL_OFF   19584
#define XSH_OFF  39168
#define XSL_OFF  72448
#define SMEM_SZ  105728

#define NSLOT    2048             // 128-row-granular mean partial slots

// ---------------------------------------------------------------------------
// Device scratch (no cudaMalloc allowed)
// ---------------------------------------------------------------------------
__device__ float g_w[W_LEN];
__device__ __align__(16) unsigned short g_wh[WBUF];
__device__ __align__(16) unsigned short g_wl[WBUF];
__device__ __align__(16) unsigned short gxph[B_N * XPITCH];   // frag-packed
__device__ __align__(16) unsigned short gxpl[B_N * XPITCH];
__device__ float g_part2[B_N * NSLOT];
__device__ float g_scale[B_N];

// ---------------------------------------------------------------------------
// Helpers
// ---------------------------------------------------------------------------
__device__ __forceinline__ uint32_t pk(const unsigned short* p) {
    return (uint32_t)p[0] | ((uint32_t)p[1] << 16);
}
__device__ __forceinline__ void mma16816(float* d, uint32_t a0, uint32_t a1,
                                         uint32_t a2, uint32_t a3,
                                         uint32_t b0, uint32_t b1) {
    asm volatile(
        "mma.sync.aligned.m16n8k16.row.col.f32.bf16.bf16.f32 "
        "{%0,%1,%2,%3}, {%4,%5,%6,%7}, {%8,%9}, {%0,%1,%2,%3};"
        : "+f"(d[0]), "+f"(d[1]), "+f"(d[2]), "+f"(d[3])
        : "r"(a0), "r"(a1), "r"(a2), "r"(a3), "r"(b0), "r"(b1));
}

// ---------------------------------------------------------------------------
// Prep 1: softmax over temporal_weights, flipped -> g_w
// ---------------------------------------------------------------------------
__global__ void softmax_flip_kernel(const float* __restrict__ tw) {
    __shared__ float red[256];
    __shared__ float s_max, s_invsum;
    const int tid = threadIdx.x;

    float m = -1e30f;
    for (int i = tid; i < W_LEN; i += 256) m = fmaxf(m, tw[i]);
    red[tid] = m; __syncthreads();
    for (int s = 128; s > 0; s >>= 1) {
        if (tid < s) red[tid] = fmaxf(red[tid], red[tid + s]);
        __syncthreads();
    }
    if (tid == 0) s_max = red[0];
    __syncthreads();
    const float mx = s_max;
    __syncthreads();

    float sum = 0.f;
    for (int i = tid; i < W_LEN; i += 256) sum += expf(tw[i] - mx);
    red[tid] = sum; __syncthreads();
    for (int s = 128; s > 0; s >>= 1) {
        if (tid < s) red[tid] += red[tid + s];
        __syncthreads();
    }
    if (tid == 0) s_invsum = 1.f / red[0];
    __syncthreads();
    const float inv = s_invsum;

    for (int i = tid; i < W_LEN; i += 256)
        g_w[W_LEN - 1 - i] = expf(tw[i] - mx) * inv;
}

// ---------------------------------------------------------------------------
// Prep 2: guarded split-bf16 weight buffer
// ---------------------------------------------------------------------------
__global__ void wsplit_kernel() {
    for (int i = threadIdx.x; i < WBUF; i += 256) {
        int wi = i - WOFF;
        float v = (wi >= 0 && wi < W_LEN) ? g_w[wi] : 0.f;
        __nv_bfloat16 h = __float2bfloat16(v);
        float lo = v - __bfloat162float(h);
        __nv_bfloat16 l = __float2bfloat16(lo);
        g_wh[i] = __bfloat16_as_ushort(h);
        g_wl[i] = __bfloat16_as_ushort(l);
    }
}

// ---------------------------------------------------------------------------
// Prep 3: edge-padded split-bf16 input planes, FRAGMENT-PACKED.
// Also zeroes mean-partial slots each launch (graph-replay safe).
// ---------------------------------------------------------------------------
__global__ void xsplit_kernel(const float* __restrict__ att) {
    long long idx = (long long)blockIdx.x * blockDim.x + threadIdx.x;
    if (idx < B_N * NSLOT) g_part2[idx] = 0.f;
    if (idx >= (long long)B_N * XPITCH) return;
    int n = (int)(idx / XPITCH);
    int u = (int)(idx - (long long)n * XPITCH);
    int t = u - PAD;
    t = min(max(t, 0), T_LEN - 1);
    float v = att[n * T_LEN + t];
    __nv_bfloat16 h = __float2bfloat16(v);
    float lo = v - __bfloat162float(h);
    __nv_bfloat16 l = __float2bfloat16(lo);
    int g = u >> 4, p = u & 15;
    int np = (p < 8) ? (((p >> 1) << 2) | (p & 1))
                     : ((((p - 8) >> 1) << 2) | 2 | (p & 1));
    size_t dst = (size_t)n * XPITCH + (g << 4) + np;
    gxph[dst] = __bfloat16_as_ushort(h);
    gxpl[dst] = __bfloat16_as_ushort(l);
}

// ---------------------------------------------------------------------------
// GEMM body, IB m-blocks per warp (IB=4 -> 512-row tile, IB=3 -> 384-row).
// r9 machinery: single-buffer LDG/STS staging, ring-4 Toeplitz A chaining,
// LDS.64 frag-packed B, 3-pass split-bf16, per-warp band skip, fused mean.
// ---------------------------------------------------------------------------
template <int IB>
__device__ __forceinline__ void gemm_body(float* __restrict__ out, int t0,
                                          unsigned char* smem) {
    constexpr int MT = 128 * IB;
    constexpr int PITCH = MT + 8;
    unsigned short* wh = (unsigned short*)(smem + WH_OFF);
    unsigned short* wl = (unsigned short*)(smem + WL_OFF);
    unsigned short* xsh = (unsigned short*)(smem + XSH_OFF);
    unsigned short* xsl = (unsigned short*)(smem + XSL_OFF);

    const int tid  = threadIdx.x;
    const int warp = tid >> 5;
    const int lane = tid & 31;
    const int Wbase = warp * 16 * IB;
    const int r0 = lane >> 2;
    const int c0 = (lane & 3) * 2;
    const int smin = IB * warp;
    const int smax = IB * (warp + 1) + 539;

    for (int i = tid; i < WBUF / 8; i += 256) {
        ((uint4*)wh)[i] = ((const uint4*)g_wh)[i];
        ((uint4*)wl)[i] = ((const uint4*)g_wl)[i];
    }

    const unsigned short* bh0 = xsh + (lane >> 2) * XSROW + 2 * c0;
    const unsigned short* bh1 = xsh + ((lane >> 2) + 8) * XSROW + 2 * c0;
    const unsigned short* bl0 = xsl + (lane >> 2) * XSROW + 2 * c0;
    const unsigned short* bl1 = xsl + ((lane >> 2) + 8) * XSROW + 2 * c0;

    float acc[IB][2][4];
#pragma unroll
    for (int i = 0; i < IB; i++)
#pragma unroll
        for (int nb = 0; nb < 2; nb++)
#pragma unroll
            for (int q = 0; q < 4; q++) acc[i][nb][q] = 0.f;

    uint32_t Ah[4][3], Al[4][3];
#pragma unroll
    for (int i = 0; i < 4; i++)
#pragma unroll
        for (int q = 0; q < 3; q++) { Ah[i][q] = 0u; Al[i][q] = 0u; }

    for (int chunk = 0; chunk < NCHK; ++chunk) {
        __syncthreads();
        {
            const int xbase = t0 + chunk * JT;
            for (int it = tid; it < 4096; it += 256) {
                int plane = it >> 11;
                int r = (it >> 7) & 15;
                int q = it & 127;
                const unsigned short* src =
                    (plane ? gxpl : gxph) + (size_t)r * XPITCH + xbase + q * 8;
                unsigned short* dst = (plane ? xsl : xsh) + r * XSROW + q * 8;
                *(uint4*)dst = *(const uint4*)src;
            }
        }
        __syncthreads();

        const int s0 = chunk * 64;
        int sl_lo = smin - s0; if (sl_lo < 0) sl_lo = 0;
        int sl_hi = smax - s0; if (sl_hi > 63) sl_hi = 63;
        if (sl_lo > sl_hi) continue;

        uint32_t pAh, pAl;
        {
            const int base0 = WOFF + 16 * (s0 + sl_lo) - Wbase + c0 - r0;
            pAh = pk(wh + base0 - 8);
            pAl = pk(wl + base0 - 8);
        }

#pragma unroll 4
        for (int sl = sl_lo; sl <= sl_hi; ++sl) {
            const int s = s0 + sl;
            const int slot = sl & 3;
            const int base = WOFF + 16 * s - Wbase + c0 - r0;
            Ah[slot][1] = pAh;               Al[slot][1] = pAl;
            Ah[slot][0] = pk(wh + base);     Al[slot][0] = pk(wl + base);
            Ah[slot][2] = pk(wh + base + 8); Al[slot][2] = pk(wl + base + 8);
            pAh = Ah[slot][2];               pAl = Al[slot][2];

            const int jj = 16 * sl;
            uint2 vh0 = *(const uint2*)(bh0 + jj);
            uint2 vh1 = *(const uint2*)(bh1 + jj);
            uint2 vl0 = *(const uint2*)(bl0 + jj);
            uint2 vl1 = *(const uint2*)(bl1 + jj);
            uint32_t bh[2][2] = {{vh0.x, vh0.y}, {vh1.x, vh1.y}};
            uint32_t bl[2][2] = {{vl0.x, vl0.y}, {vl1.x, vl1.y}};

#pragma unroll
            for (int ib = 0; ib < IB; ++ib) {
                const int sig = (sl - ib) & 3;
                mma16816(acc[ib][0], Ah[sig][0], Ah[sig][1], Ah[sig][2], Ah[sig][0], bh[0][0], bh[0][1]);
                mma16816(acc[ib][1], Ah[sig][0], Ah[sig][1], Ah[sig][2], Ah[sig][0], bh[1][0], bh[1][1]);
            }
#pragma unroll
            for (int ib = 0; ib < IB; ++ib) {
                const int sig = (sl - ib) & 3;
                mma16816(acc[ib][0], Ah[sig][0], Ah[sig][1], Ah[sig][2], Ah[sig][0], bl[0][0], bl[0][1]);
                mma16816(acc[ib][1], Ah[sig][0], Ah[sig][1], Ah[sig][2], Ah[sig][0], bl[1][0], bl[1][1]);
            }
#pragma unroll
            for (int ib = 0; ib < IB; ++ib) {
                const int sig = (sl - ib) & 3;
                mma16816(acc[ib][0], Al[sig][0], Al[sig][1], Al[sig][2], Al[sig][0], bh[0][0], bh[0][1]);
                mma16816(acc[ib][1], Al[sig][0], Al[sig][1], Al[sig][2], Al[sig][0], bh[1][0], bh[1][1]);
            }
        }
    }

    // ---- epilogue: transpose via smt (over dead weights), fused mean ----
    __syncthreads();
    float* smt = (float*)smem;               // 16 x PITCH floats
#pragma unroll
    for (int ib = 0; ib < IB; ++ib) {
        const int mloc = Wbase + ib * 16 + r0;
#pragma unroll
        for (int nb = 0; nb < 2; ++nb) {
            const int n = c0 + nb * 8;
            smt[n * PITCH + mloc]           = acc[ib][nb][0];
            smt[(n + 1) * PITCH + mloc]     = acc[ib][nb][1];
            smt[n * PITCH + mloc + 8]       = acc[ib][nb][2];
            smt[(n + 1) * PITCH + mloc + 8] = acc[ib][nb][3];
        }
    }
    __syncthreads();

    // deterministic per-CTA per-n partial sums (warp w -> n=w and n=w+8)
    {
        float sa = 0.f, sb = 0.f;
        for (int m = lane; m < MT; m += 32) {
            sa += smt[warp * PITCH + m];
            sb += smt[(warp + 8) * PITCH + m];
        }
#pragma unroll
        for (int o = 16; o > 0; o >>= 1) {
            sa += __shfl_xor_sync(0xFFFFFFFFu, sa, o);
            sb += __shfl_xor_sync(0xFFFFFFFFu, sb, o);
        }
        if (lane == 0) {
            int slot = t0 >> 7;              // unique per CTA (t0 mult of 128)
            g_part2[warp * NSLOT + slot] = sa;
            g_part2[(warp + 8) * NSLOT + slot] = sb;
        }
    }

    for (int e = tid; e < B_N * MT; e += 256) {
        int n = e / MT;
        int mloc = e - n * MT;
        out[n * T_LEN + t0 + mloc] = smt[n * PITCH + mloc];
    }
}

__global__ void __launch_bounds__(256, 2) gemm_kernel(float* __restrict__ out) {
    extern __shared__ unsigned char smem[];
    const int bid = blockIdx.x;
    if (bid < N1) {
        gemm_body<4>(out, bid * 512, smem);
    } else {
        gemm_body<3>(out, N1 * 512 + (bid - N1) * 384, smem);
    }
}

// ---------------------------------------------------------------------------
// MLP: parallel mean gather (16 warps, one per batch) + tiny MLP
// ---------------------------------------------------------------------------
__global__ void mlp_kernel(const float* __restrict__ meta,
                           const float* __restrict__ W1, const float* __restrict__ b1,
                           const float* __restrict__ W2, const float* __restrict__ b2,
                           const float* __restrict__ W3, const float* __restrict__ b3,
                           const float* __restrict__ cs) {
    __shared__ float s_mean[B_N];
    const int tid = threadIdx.x;
    const int n = tid >> 5, l = tid & 31;

    float s = 0.f;
    for (int j = l; j < NSLOT; j += 32) s += g_part2[n * NSLOT + j];
#pragma unroll
    for (int o = 16; o > 0; o >>= 1) s += __shfl_xor_sync(0xFFFFFFFFu, s, o);
    if (l == 0) s_mean[n] = s;
    __syncthreads();

    const int b = tid;
    if (b >= B_N) return;

    float ci[1 + F_META];
    ci[0] = s_mean[b] / (float)T_LEN;
    for (int i = 0; i < F_META; ++i) ci[1 + i] = meta[b * F_META + i];

    float h1[32];
    for (int j = 0; j < 32; ++j) {
        float a = b1[j];
        for (int i = 0; i < 1 + F_META; ++i) a = fmaf(W1[j * (1 + F_META) + i], ci[i], a);
        h1[j] = fmaxf(a, 0.f);
    }
    float h2[16];
    for (int j = 0; j < 16; ++j) {
        float a = b2[j];
        for (int i = 0; i < 32; ++i) a = fmaf(W2[j * 32 + i], h1[i], a);
        h2[j] = fmaxf(a, 0.f);
    }
    float f = b3[0];
    for (int i = 0; i < 16; ++i) f = fmaf(W3[i], h2[i], f);
    g_scale[b] = 1.f + cs[0] * tanhf(f);
}

__global__ void scale_kernel(float* __restrict__ out) {
    int idx = blockIdx.x * blockDim.x + threadIdx.x;
    const int per_b = T_LEN / 4;
    int b = idx / per_b;
    float s = g_scale[b];
    float4* o4 = (float4*)out;
    float4 v = o4[idx];
    v.x *= s; v.y *= s; v.z *= s; v.w *= s;
    o4[idx] = v;
}

// ---------------------------------------------------------------------------
// Launch
// ---------------------------------------------------------------------------
extern "C" void kernel_launch(void* const* d_in, const int* in_sizes, int n_in,
                              void* d_out, int out_size) {
    const float* att  = (const float*)d_in[0];
    const float* meta = (const float*)d_in[1];
    const float* tw   = (const float*)d_in[2];
    const float* W1   = (const float*)d_in[3];
    const float* b1   = (const float*)d_in[4];
    const float* W2   = (const float*)d_in[5];
    const float* b2   = (const float*)d_in[6];
    const float* W3   = (const float*)d_in[7];
    const float* b3   = (const float*)d_in[8];
    const float* cs   = (const float*)d_in[9];
    float* out = (float*)d_out;

    cudaFuncSetAttribute(gemm_kernel, cudaFuncAttributeMaxDynamicSharedMemorySize, SMEM_SZ);

    softmax_flip_kernel<<<1, 256>>>(tw);
    wsplit_kernel<<<1, 256>>>();
    {
        long long tot = (long long)B_N * XPITCH;
        int blocks = (int)((tot + 255) / 256);
        xsplit_kernel<<<blocks, 256>>>(att);
    }
    gemm_kernel<<<N1 + N2, 256, SMEM_SZ>>>(out);
    mlp_kernel<<<1, 512>>>(meta, W1, b1, W2, b2, W3, b3, cs);
    scale_kernel<<<(B_N * T_LEN / 4 + 255) / 256, 256>>>(out);
}